// round 14
// baseline (speedup 1.0000x reference)
#include <cuda_runtime.h>
#include <cuda_bf16.h>
#include <cstdint>

#define NN 60000
#define EE 480000
#define CC 256
#define RR 16
#define XWW 8192
#define NB1 (NN*RR)
#define AGGROWS 245760000
#define MAXT 7600
#define PITCH 40
// dynamic smem layout (bytes): Ah 0..10240, Al 10240..20480,
// stage s in {0,1}: Astage 20480+s*38912 (18432B, pitch 36 floats),
//                   Bh 38912+s*38912 (10240), Bl +10240
#define SM_AST 20480
#define SM_BH  38912
#define SM_STG 38912
#define DSM    98304

// ---------------- scratch ----------------
__device__ float g_x   [(size_t)NN*CC];
__device__ float g_xw  [(size_t)NN*XWW];
__device__ float g_h1  [(size_t)NN*CC];
__device__ float g_h2  [(size_t)NN*CC];
__device__ float g_h1b [(size_t)NN*CC];
__device__ float g_h2b [(size_t)NN*CC];
__device__ float g_agg1[(size_t)NN*CC];
__device__ float g_agg2[(size_t)NN*CC];
__device__ float g_m1  [(size_t)NN*128];
__device__ float g_m2  [(size_t)NN*64];
__device__ int   g_cnt1[NB1];
__device__ int   g_cnt3[NB1];
__device__ int   g_slot[2*NB1];
__device__ int   g_rowdst[2*NB1];
__device__ int   g_relcnt[32];
__device__ int   g_relfill[32];
__device__ int   g_tr[2*MAXT];
__device__ int   g_tb[2*MAXT];
__device__ int   g_tn[2*MAXT];
__device__ int   g_ntiles[2];
__device__ int   g_reloff[34];
__device__ __nv_bfloat16 g_wth[(size_t)XWW*CC];
__device__ __nv_bfloat16 g_wtl[(size_t)XWW*CC];
__device__ __nv_bfloat16 g_bh [3*65536];
__device__ __nv_bfloat16 g_bl [3*65536];

// ---------------- helpers ----------------
__device__ __forceinline__ uint32_t smem_u32(const void* p) {
    uint32_t a;
    asm("{ .reg .u64 t; cvta.to.shared.u64 t, %1; cvt.u32.u64 %0, t; }" : "=r"(a) : "l"(p));
    return a;
}
#define CPA16(d, g, p) \
    asm volatile("cp.async.cg.shared.global [%0], [%1], 16, %2;" \
                 :: "r"(d), "l"(g), "r"((p) ? 16 : 0))
#define CPA_COMMIT() asm volatile("cp.async.commit_group;")
#define CPA_WAIT1()  asm volatile("cp.async.wait_group 1;")

__device__ __forceinline__ void ldx4(uint32_t addr, uint32_t& r0, uint32_t& r1,
                                     uint32_t& r2, uint32_t& r3) {
    asm volatile("ldmatrix.sync.aligned.m8n8.x4.shared.b16 {%0,%1,%2,%3}, [%4];"
                 : "=r"(r0), "=r"(r1), "=r"(r2), "=r"(r3) : "r"(addr));
}
__device__ __forceinline__ void mma16816(float* c, const uint32_t* a, const uint32_t* b) {
    asm volatile(
        "mma.sync.aligned.m16n8k16.row.col.f32.bf16.bf16.f32 "
        "{%0,%1,%2,%3}, {%4,%5,%6,%7}, {%8,%9}, {%0,%1,%2,%3};"
        : "+f"(c[0]), "+f"(c[1]), "+f"(c[2]), "+f"(c[3])
        : "r"(a[0]), "r"(a[1]), "r"(a[2]), "r"(a[3]), "r"(b[0]), "r"(b[1]));
}
__device__ __forceinline__ void split4(float4 v, uint2& ph, uint2& pl) {
    __nv_bfloat16 h0 = __float2bfloat16(v.x), h1 = __float2bfloat16(v.y);
    __nv_bfloat16 h2 = __float2bfloat16(v.z), h3 = __float2bfloat16(v.w);
    __nv_bfloat16 l0 = __float2bfloat16(v.x - __bfloat162float(h0));
    __nv_bfloat16 l1 = __float2bfloat16(v.y - __bfloat162float(h1));
    __nv_bfloat16 l2 = __float2bfloat16(v.z - __bfloat162float(h2));
    __nv_bfloat16 l3 = __float2bfloat16(v.w - __bfloat162float(h3));
    ph.x = (uint32_t)__bfloat16_as_ushort(h0) | ((uint32_t)__bfloat16_as_ushort(h1) << 16);
    ph.y = (uint32_t)__bfloat16_as_ushort(h2) | ((uint32_t)__bfloat16_as_ushort(h3) << 16);
    pl.x = (uint32_t)__bfloat16_as_ushort(l0) | ((uint32_t)__bfloat16_as_ushort(l1) << 16);
    pl.y = (uint32_t)__bfloat16_as_ushort(l2) | ((uint32_t)__bfloat16_as_ushort(l3) << 16);
}

// ---------------- small kernels (unchanged from round 12) ----------------
__global__ void k_zero() {
    int i = blockIdx.x * blockDim.x + threadIdx.x;
    int stride = gridDim.x * blockDim.x;
    const int nf = NN * CC;
    for (int j = i; j < nf; j += stride) {
        g_h1[j] = 0.f; g_h2[j] = 0.f; g_agg1[j] = 0.f; g_agg2[j] = 0.f;
    }
    for (int j = i; j < NB1; j += stride) { g_cnt1[j] = 0; g_cnt3[j] = 0; }
    if (i < 32) { g_relcnt[i] = 0; g_relfill[i] = 0; }
}

__global__ void k_hist(const int* __restrict__ dst, const int* __restrict__ et1,
                       const int* __restrict__ et3) {
    int e = blockIdx.x * blockDim.x + threadIdx.x;
    if (e >= EE) return;
    int d = dst[e];
    atomicAdd(&g_cnt1[d * RR + et1[e]], 1);
    atomicAdd(&g_cnt3[d * RR + et3[e]], 1);
}

__global__ void k_nonempty() {
    int idx = blockIdx.x * blockDim.x + threadIdx.x;
    if (idx >= 2 * NB1) return;
    int q = idx / NB1, b = idx - q * NB1;
    int c = q ? g_cnt3[b] : g_cnt1[b];
    if (c > 0) atomicAdd(&g_relcnt[q * 16 + (b & 15)], 1);
}

__global__ void k_buildtiles() {
    __shared__ int s_off[32], s_toff[32];
    int t = threadIdx.x;
    if (t == 0) {
        for (int q = 0; q < 2; q++) {
            int off = 0, toff = 0;
            for (int r = 0; r < 16; r++) {
                int i = q * 16 + r;
                s_off[i] = off; s_toff[i] = toff;
                int c = g_relcnt[i];
                g_reloff[q * 17 + r] = off;
                off += c;
                toff += (c + 127) >> 7;
            }
            g_reloff[q * 17 + 16] = off;
            g_ntiles[q] = toff;
        }
    }
    __syncthreads();
    int q = t >> 4, r = t & 15;
    int c = g_relcnt[t];
    int base = s_off[t], tile0 = s_toff[t];
    int nt = (c + 127) >> 7;
    for (int k = 0; k < nt; k++) {
        int idx = q * MAXT + tile0 + k;
        g_tr[idx] = r;
        g_tb[idx] = base + k * 128;
        g_tn[idx] = min(128, c - k * 128);
    }
}

__global__ void k_zeroagg() {
    size_t n0 = (size_t)g_reloff[16] * 64;
    size_t n1 = (size_t)g_reloff[33] * 64;
    size_t stride = (size_t)gridDim.x * blockDim.x;
    size_t i0 = (size_t)blockIdx.x * blockDim.x + threadIdx.x;
    float4 z = make_float4(0.f, 0.f, 0.f, 0.f);
    float4* p0 = (float4*)g_xw;
    float4* p1 = (float4*)(g_xw + (size_t)AGGROWS);
    for (size_t i = i0; i < n0; i += stride) p0[i] = z;
    for (size_t i = i0; i < n1; i += stride) p1[i] = z;
}

__global__ void k_slot() {
    int idx = blockIdx.x * blockDim.x + threadIdx.x;
    if (idx >= 2 * NB1) return;
    int q = idx / NB1, b = idx - q * NB1;
    int c = q ? g_cnt3[b] : g_cnt1[b];
    if (c <= 0) return;
    int r = b & 15;
    int s = g_reloff[q * 17 + r] + atomicAdd(&g_relfill[q * 16 + r], 1);
    g_slot[idx] = s;
    g_rowdst[q * NB1 + s] = b >> 4;
}

__global__ void k_cvtX(const float* __restrict__ enc, const int* __restrict__ spk,
                       const float* __restrict__ table) {
    int i = blockIdx.x * blockDim.x + threadIdx.x;
    if (i >= NN * CC / 4) return;
    int n = i >> 6, c = i & 63;
    float4 e = ((const float4*)enc)[i];
    float4 t = ((const float4*)table)[spk[n] * 64 + c];
    e.x += t.x; e.y += t.y; e.z += t.z; e.w += t.w;
    ((float4*)g_x)[i] = e;
}

__global__ void k_packW(const float* __restrict__ bases1, const float* __restrict__ comp1,
                        const float* __restrict__ bases3, const float* __restrict__ comp3) {
    int r = blockIdx.x;
    int i0 = blockIdx.y * 8;
    int o = threadIdx.x;
    const float* bases = (r < 16) ? bases1 : bases3;
    const float* comp  = (r < 16) ? comp1  : comp3;
    int rr = r & 15;
    float cf[8];
#pragma unroll
    for (int b = 0; b < 8; b++) cf[b] = comp[rr * 8 + b];
    for (int i = i0; i < i0 + 8; i++) {
        float acc = 0.f;
#pragma unroll
        for (int b = 0; b < 8; b++) acc += cf[b] * bases[b * 65536 + i * 256 + o];
        __nv_bfloat16 h = __float2bfloat16(acc);
        __nv_bfloat16 l = __float2bfloat16(acc - __bfloat162float(h));
        size_t oi = (size_t)(r * 256 + o) * CC + i;
        g_wth[oi] = h; g_wtl[oi] = l;
    }
}

__global__ void k_cvtB(const float* __restrict__ in, int K, int N, int off) {
    int idx = blockIdx.x * blockDim.x + threadIdx.x;
    if (idx >= N * K) return;
    int n = idx / K, k = idx - n * K;
    float v = in[(size_t)k * N + n];
    __nv_bfloat16 h = __float2bfloat16(v);
    __nv_bfloat16 l = __float2bfloat16(v - __bfloat162float(h));
    g_bh[off + idx] = h; g_bl[off + idx] = l;
}

__global__ void k_edgeagg(const int* __restrict__ src, const int* __restrict__ dst,
                          const int* __restrict__ et, const int* __restrict__ est) {
    int e = blockIdx.x * (blockDim.x >> 5) + (threadIdx.x >> 5);
    int lane = threadIdx.x & 31;
    if (e >= EE) return;
    int s = src[e], d = dst[e];
    int b1 = d * RR + et[e], b3 = d * RR + est[e];
    int s1 = g_slot[b1], s3 = g_slot[NB1 + b3];
    float n1 = 1.f / (float)g_cnt1[b1];
    float n3 = 1.f / (float)g_cnt3[b3];
    const float4* xr = (const float4*)(g_x + (size_t)s * CC);
    float* a1 = g_xw + (size_t)s1 * CC;
    float* a3 = g_xw + (size_t)AGGROWS + (size_t)s3 * CC;
#pragma unroll
    for (int k = 0; k < 2; k++) {
        int o4 = lane + k * 32;
        float4 v = xr[o4];
        asm volatile("red.global.add.v4.f32 [%0], {%1,%2,%3,%4};"
                     :: "l"(a1 + o4 * 4), "f"(v.x * n1), "f"(v.y * n1),
                        "f"(v.z * n1), "f"(v.w * n1) : "memory");
        asm volatile("red.global.add.v4.f32 [%0], {%1,%2,%3,%4};"
                     :: "l"(a3 + o4 * 4), "f"(v.x * n3), "f"(v.y * n3),
                        "f"(v.z * n3), "f"(v.w * n3) : "memory");
    }
}

__global__ void k_scatter(const int* __restrict__ src, const int* __restrict__ dst,
                          const float* __restrict__ h, float* __restrict__ agg) {
    int e = blockIdx.x * (blockDim.x >> 5) + (threadIdx.x >> 5);
    int lane = threadIdx.x & 31;
    if (e >= EE) return;
    const float4* hr = (const float4*)(h + (size_t)src[e] * CC);
    float* ap = agg + (size_t)dst[e] * CC;
#pragma unroll
    for (int k = 0; k < 2; k++) {
        int o4 = lane + k * 32;
        float4 v = hr[o4];
        asm volatile("red.global.add.v4.f32 [%0], {%1,%2,%3,%4};"
                     :: "l"(ap + o4 * 4), "f"(v.x), "f"(v.y), "f"(v.z), "f"(v.w) : "memory");
    }
}

// ---------------- tile-list RGCN GEMM + scatter (cp.async pipelined) ----------------
__global__ __launch_bounds__(256) void tcrgemm() {
    int q = blockIdx.z;
    if ((int)blockIdx.x >= g_ntiles[q]) return;
    extern __shared__ __align__(16) char dynsm[];
    __nv_bfloat16* sAh = (__nv_bfloat16*)dynsm;
    __nv_bfloat16* sAl = (__nv_bfloat16*)(dynsm + 10240);
    uint32_t base = smem_u32(dynsm);
    uint32_t uA0 = base, uA1 = base + 10240;

    int tid = threadIdx.x, wid = tid >> 5, lane = tid & 31;
    int ti = q * MAXT + blockIdx.x;
    int rel = g_tr[ti], mbase = g_tb[ti], mrows = g_tn[ti];
    const float* A = g_xw + (size_t)q * AGGROWS + (size_t)mbase * CC;
    const __nv_bfloat16* Bh = g_wth + ((size_t)(q * 16 + rel) * 256 + blockIdx.y * 128) * CC;
    const __nv_bfloat16* Bl = g_wtl + ((size_t)(q * 16 + rel) * 256 + blockIdx.y * 128) * CC;
    float* H = q ? g_h2 : g_h1;
    const int* rowdst = g_rowdst + q * NB1 + mbase;

    int wm = (wid >> 2) * 64, wn = (wid & 3) * 32;
    float acc[4][4][4];
#pragma unroll
    for (int i = 0; i < 4; i++)
#pragma unroll
        for (int j = 0; j < 4; j++)
#pragma unroll
            for (int k = 0; k < 4; k++) acc[i][j][k] = 0.f;

    int arow = tid >> 1, ahalf = tid & 1;

    auto issue = [&](int ch, int s) {
        int k0 = ch << 5;
        uint32_t ua  = base + SM_AST + s * SM_STG;
        uint32_t ubh = base + SM_BH  + s * SM_STG;
        uint32_t ubl = ubh + 10240;
#pragma unroll
        for (int i = 0; i < 4; i++) {
            int idx = tid + (i << 8);
            int row = idx >> 3, c2 = idx & 7;
            const float* g = A + (size_t)row * CC + k0 + c2 * 4;
            CPA16(ua + row * 144 + c2 * 16, g, row < mrows);
        }
#pragma unroll
        for (int i = 0; i < 2; i++) {
            int idx = tid + (i << 8);
            int row = idx >> 2, c2 = idx & 3;
            const __nv_bfloat16* gh = Bh + (size_t)row * CC + k0 + c2 * 8;
            const __nv_bfloat16* gl = Bl + (size_t)row * CC + k0 + c2 * 8;
            CPA16(ubh + row * 80 + c2 * 16, gh, true);
            CPA16(ubl + row * 80 + c2 * 16, gl, true);
        }
    };

    issue(0, 0); CPA_COMMIT();
    issue(1, 1); CPA_COMMIT();

    for (int ch = 0; ch < 8; ch++) {
        int s = ch & 1;
        CPA_WAIT1();
        __syncthreads();
        const float* ast = (const float*)(dynsm + SM_AST + s * SM_STG);
#pragma unroll
        for (int j = 0; j < 4; j++) {
            float4 f = *(const float4*)(ast + arow * 36 + ahalf * 16 + j * 4);
            uint2 ph, pl;
            split4(f, ph, pl);
            int off = arow * PITCH + ahalf * 16 + j * 4;
            *(uint2*)(sAh + off) = ph;
            *(uint2*)(sAl + off) = pl;
        }
        __syncthreads();
        uint32_t uB0 = base + SM_BH + s * SM_STG, uB1 = uB0 + 10240;
#pragma unroll
        for (int ks = 0; ks < 2; ks++) {
            int kb = ks * 32;
            uint32_t bfr[2][4][2];
#pragma unroll
            for (int pair = 0; pair < 2; pair++) {
                int nrow = wn + pair * 16 + ((lane >> 4) & 1) * 8 + (lane & 7);
                int kbyte = kb + ((lane >> 3) & 1) * 16;
                uint32_t off = nrow * (PITCH * 2) + kbyte;
                ldx4(uB0 + off, bfr[0][pair * 2][0], bfr[0][pair * 2][1],
                     bfr[0][pair * 2 + 1][0], bfr[0][pair * 2 + 1][1]);
                ldx4(uB1 + off, bfr[1][pair * 2][0], bfr[1][pair * 2][1],
                     bfr[1][pair * 2 + 1][0], bfr[1][pair * 2 + 1][1]);
            }
#pragma unroll
            for (int mt = 0; mt < 4; mt++) {
                int ar = wm + mt * 16 + (lane & 15);
                int kbyte = kb + ((lane >> 4) & 1) * 16;
                uint32_t off = ar * (PITCH * 2) + kbyte;
                uint32_t ah[4], al[4];
                ldx4(uA0 + off, ah[0], ah[1], ah[2], ah[3]);
                ldx4(uA1 + off, al[0], al[1], al[2], al[3]);
#pragma unroll
                for (int nt = 0; nt < 4; nt++) {
                    mma16816(acc[mt][nt], ah, bfr[0][nt]);
                    mma16816(acc[mt][nt], ah, bfr[1][nt]);
                    mma16816(acc[mt][nt], al, bfr[0][nt]);
                }
            }
        }
        __syncthreads();
        if (ch + 2 < 8) issue(ch + 2, s);
        CPA_COMMIT();
    }

    int tr = lane >> 2, tc = (lane & 3) * 2;
    int col0 = blockIdx.y * 128;
#pragma unroll
    for (int mt = 0; mt < 4; mt++) {
#pragma unroll
        for (int half = 0; half < 2; half++) {
            int rl = wm + mt * 16 + tr + half * 8;
            if (rl >= mrows) continue;
            int d = rowdst[rl];
            float* hp = H + (size_t)d * CC + col0 + wn;
#pragma unroll
            for (int nt = 0; nt < 4; nt++) {
                float v0 = acc[mt][nt][half * 2 + 0];
                float v1 = acc[mt][nt][half * 2 + 1];
                asm volatile("red.global.add.v2.f32 [%0], {%1,%2};"
                             :: "l"(hp + nt * 8 + tc), "f"(v0), "f"(v1) : "memory");
            }
        }
    }
}

// ---------------- multi-source fp32-A HMMA GEMM (cp.async pipelined) ----------------
__global__ __launch_bounds__(256) void hgemmM(
    int M, int Nt, int K, int ns,
    const float* __restrict__ A0, const float* __restrict__ A1, const float* __restrict__ A2,
    const __nv_bfloat16* __restrict__ B0h, const __nv_bfloat16* __restrict__ B0l,
    const __nv_bfloat16* __restrict__ B1h, const __nv_bfloat16* __restrict__ B1l,
    const __nv_bfloat16* __restrict__ B2h, const __nv_bfloat16* __restrict__ B2l,
    float* __restrict__ C, const float* __restrict__ bias, int accf, int reluf)
{
    extern __shared__ __align__(16) char dynsm[];
    __nv_bfloat16* sAh = (__nv_bfloat16*)dynsm;
    __nv_bfloat16* sAl = (__nv_bfloat16*)(dynsm + 10240);
    uint32_t base = smem_u32(dynsm);
    uint32_t uA0 = base, uA1 = base + 10240;

    int tid = threadIdx.x, wid = tid >> 5, lane = tid & 31;
    int m0 = blockIdx.y * 128, n0 = blockIdx.x * 128;
    int wm = (wid >> 2) * 64, wn = (wid & 3) * 32;

    float acc[4][4][4];
#pragma unroll
    for (int i = 0; i < 4; i++)
#pragma unroll
        for (int j = 0; j < 4; j++)
#pragma unroll
            for (int k = 0; k < 4; k++) acc[i][j][k] = 0.f;

    int arow = tid >> 1, ahalf = tid & 1;
    int kc = K >> 5, n = ns * kc;

    auto issue = [&](int t, int s) {
        int sidx = t / kc;
        int k0 = (t - sidx * kc) << 5;
        const float* As = (sidx == 0) ? A0 : (sidx == 1) ? A1 : A2;
        const __nv_bfloat16* Bhs = (sidx == 0) ? B0h : (sidx == 1) ? B1h : B2h;
        const __nv_bfloat16* Bls = (sidx == 0) ? B0l : (sidx == 1) ? B1l : B2l;
        uint32_t ua  = base + SM_AST + s * SM_STG;
        uint32_t ubh = base + SM_BH  + s * SM_STG;
        uint32_t ubl = ubh + 10240;
#pragma unroll
        for (int i = 0; i < 4; i++) {
            int idx = tid + (i << 8);
            int row = idx >> 3, c2 = idx & 7;
            const float* g = As + (size_t)(m0 + row) * K + k0 + c2 * 4;
            CPA16(ua + row * 144 + c2 * 16, g, (m0 + row) < M);
        }
#pragma unroll
        for (int i = 0; i < 2; i++) {
            int idx = tid + (i << 8);
            int row = idx >> 2, c2 = idx & 3;
            bool v = (n0 + row) < Nt;
            const __nv_bfloat16* gh = Bhs + (size_t)(n0 + row) * K + k0 + c2 * 8;
            const __nv_bfloat16* gl = Bls + (size_t)(n0 + row) * K + k0 + c2 * 8;
            CPA16(ubh + row * 80 + c2 * 16, gh, v);
            CPA16(ubl + row * 80 + c2 * 16, gl, v);
        }
    };

    issue(0, 0); CPA_COMMIT();
    if (n > 1) issue(1, 1);
    CPA_COMMIT();

    for (int ch = 0; ch < n; ch++) {
        int s = ch & 1;
        CPA_WAIT1();
        __syncthreads();
        const float* ast = (const float*)(dynsm + SM_AST + s * SM_STG);
#pragma unroll
        for (int j = 0; j < 4; j++) {
            float4 f = *(const float4*)(ast + arow * 36 + ahalf * 16 + j * 4);
            uint2 ph, pl;
            split4(f, ph, pl);
            int off = arow * PITCH + ahalf * 16 + j * 4;
            *(uint2*)(sAh + off) = ph;
            *(uint2*)(sAl + off) = pl;
        }
        __syncthreads();
        uint32_t uB0 = base + SM_BH + s * SM_STG, uB1 = uB0 + 10240;
#pragma unroll
        for (int ks = 0; ks < 2; ks++) {
            int kb = ks * 32;
            uint32_t bfr[2][4][2];
#pragma unroll
            for (int pair = 0; pair < 2; pair++) {
                int nrow = wn + pair * 16 + ((lane >> 4) & 1) * 8 + (lane & 7);
                int kbyte = kb + ((lane >> 3) & 1) * 16;
                uint32_t off = nrow * (PITCH * 2) + kbyte;
                ldx4(uB0 + off, bfr[0][pair * 2][0], bfr[0][pair * 2][1],
                     bfr[0][pair * 2 + 1][0], bfr[0][pair * 2 + 1][1]);
                ldx4(uB1 + off, bfr[1][pair * 2][0], bfr[1][pair * 2][1],
                     bfr[1][pair * 2 + 1][0], bfr[1][pair * 2 + 1][1]);
            }
#pragma unroll
            for (int mt = 0; mt < 4; mt++) {
                int ar = wm + mt * 16 + (lane & 15);
                int kbyte = kb + ((lane >> 4) & 1) * 16;
                uint32_t off = ar * (PITCH * 2) + kbyte;
                uint32_t ah[4], al[4];
                ldx4(uA0 + off, ah[0], ah[1], ah[2], ah[3]);
                ldx4(uA1 + off, al[0], al[1], al[2], al[3]);
#pragma unroll
                for (int nt = 0; nt < 4; nt++) {
                    mma16816(acc[mt][nt], ah, bfr[0][nt]);
                    mma16816(acc[mt][nt], ah, bfr[1][nt]);
                    mma16816(acc[mt][nt], al, bfr[0][nt]);
                }
            }
        }
        __syncthreads();
        if (ch + 2 < n) issue(ch + 2, s);
        CPA_COMMIT();
    }

    int tr = lane >> 2, tc = (lane & 3) * 2;
#pragma unroll
    for (int mt = 0; mt < 4; mt++) {
#pragma unroll
        for (int nt = 0; nt < 4; nt++) {
            int c = n0 + wn + nt * 8 + tc;
            if (c >= Nt) continue;
#pragma unroll
            for (int half = 0; half < 2; half++) {
                int r = m0 + wm + mt * 16 + tr + half * 8;
                if (r >= M) continue;
                float v0 = acc[mt][nt][half * 2 + 0];
                float v1 = acc[mt][nt][half * 2 + 1];
                float* cp = C + (size_t)r * Nt + c;
                if (accf) { float2 o = *(const float2*)cp; v0 += o.x; v1 += o.y; }
                if (bias) { v0 += bias[c]; v1 += bias[c + 1]; }
                if (reluf) { v0 = fmaxf(v0, 0.f); v1 = fmaxf(v1, 0.f); }
                float2 w2 = make_float2(v0, v1);
                *(float2*)cp = w2;
            }
        }
    }
}

__global__ void k_final(const float* __restrict__ wd3, const float* __restrict__ bd3,
                        float* __restrict__ out) {
    int n = blockIdx.x * (blockDim.x >> 5) + (threadIdx.x >> 5);
    int lane = threadIdx.x & 31;
    if (n >= NN) return;
    const float* m = g_m2 + (size_t)n * 64;
    float s = m[lane] * wd3[lane] + m[lane + 32] * wd3[lane + 32];
#pragma unroll
    for (int o = 16; o; o >>= 1) s += __shfl_xor_sync(0xffffffffu, s, o);
    if (lane == 0) out[n] = s + bd3[0];
}

// ---------------- host ----------------
static __nv_bfloat16 *pbh, *pbl;

static void gemmM(int M, int Nt, int K, int ns,
                  const float* A0, const float* A1, const float* A2,
                  int off0, int off1, int off2,
                  float* C, const float* bias, int acc, int relu) {
    dim3 g((Nt + 127) / 128, (M + 127) / 128);
    hgemmM<<<g, 256, DSM>>>(M, Nt, K, ns, A0, A1, A2,
                            pbh + off0, pbl + off0, pbh + off1, pbl + off1,
                            pbh + off2, pbl + off2, C, bias, acc, relu);
}

extern "C" void kernel_launch(void* const* d_in, const int* in_sizes, int n_in,
                              void* d_out, int out_size) {
    const float* enc     = (const float*)d_in[0];
    const int*   speaker = (const int*)d_in[1];
    const int*   eidx    = (const int*)d_in[2];
    const int*   src     = eidx;
    const int*   dst     = eidx + EE;
    const int*   et      = (const int*)d_in[3];
    const int*   est     = (const int*)d_in[4];
    const float* spk_tab = (const float*)d_in[5];
    const float* comp1   = (const float*)d_in[6];
    const float* bases1  = (const float*)d_in[7];
    const float* root1   = (const float*)d_in[8];
    const float* b1      = (const float*)d_in[9];
    const float* w2_rel  = (const float*)d_in[10];
    const float* b2      = (const float*)d_in[11];
    const float* w2_root = (const float*)d_in[12];
    const float* comp3   = (const float*)d_in[13];
    const float* bases3  = (const float*)d_in[14];
    const float* root3   = (const float*)d_in[15];
    const float* b3      = (const float*)d_in[16];
    const float* w4_rel  = (const float*)d_in[17];
    const float* b4      = (const float*)d_in[18];
    const float* w4_root = (const float*)d_in[19];
    const float* wd1     = (const float*)d_in[20];
    const float* bd1     = (const float*)d_in[21];
    const float* wd2     = (const float*)d_in[22];
    const float* bd2     = (const float*)d_in[23];
    const float* wd3     = (const float*)d_in[24];
    const float* bd3     = (const float*)d_in[25];
    float* out = (float*)d_out;

    float *px, *ph1, *ph2, *ph1b, *ph2b, *pa1, *pa2, *pm1, *pm2;
    cudaGetSymbolAddress((void**)&px,   g_x);
    cudaGetSymbolAddress((void**)&ph1,  g_h1);
    cudaGetSymbolAddress((void**)&ph2,  g_h2);
    cudaGetSymbolAddress((void**)&ph1b, g_h1b);
    cudaGetSymbolAddress((void**)&ph2b, g_h2b);
    cudaGetSymbolAddress((void**)&pa1,  g_agg1);
    cudaGetSymbolAddress((void**)&pa2,  g_agg2);
    cudaGetSymbolAddress((void**)&pm1,  g_m1);
    cudaGetSymbolAddress((void**)&pm2,  g_m2);
    cudaGetSymbolAddress((void**)&pbh,  g_bh);
    cudaGetSymbolAddress((void**)&pbl,  g_bl);

    cudaFuncSetAttribute(hgemmM,  cudaFuncAttributeMaxDynamicSharedMemorySize, DSM);
    cudaFuncSetAttribute(tcrgemm, cudaFuncAttributeMaxDynamicSharedMemorySize, DSM);

    const int NC4 = NN * CC / 4;
    const int B1 = 65536, B2 = 131072;

    k_zero<<<2048, 256>>>();
    k_cvtX<<<(NC4 + 255) / 256, 256>>>(enc, speaker, spk_tab);
    k_hist<<<(EE + 255) / 256, 256>>>(dst, et, est);
    k_packW<<<dim3(32, 32), 256>>>(bases1, comp1, bases3, comp3);

    // bucket compaction
    k_nonempty<<<(2 * NB1 + 255) / 256, 256>>>();
    k_buildtiles<<<1, 32>>>();
    k_zeroagg<<<8192, 256>>>();
    k_slot<<<(2 * NB1 + 255) / 256, 256>>>();

    // per-edge aggregation + compacted RGCN GEMMs
    k_edgeagg<<<(EE + 7) / 8, 256>>>(src, dst, et, est);
    tcrgemm<<<dim3(MAXT, 2, 2), 256, DSM>>>();

    // root terms: h += x@root + b
    k_cvtB<<<(CC * CC + 255) / 256, 256>>>(root1, CC, CC, 0);
    gemmM(NN, CC, CC, 1, px, nullptr, nullptr, 0, 0, 0, ph1, b1, 1, 0);
    k_cvtB<<<(CC * CC + 255) / 256, 256>>>(root3, CC, CC, 0);
    gemmM(NN, CC, CC, 1, px, nullptr, nullptr, 0, 0, 0, ph2, b3, 1, 0);

    // GraphConv aggregations
    k_scatter<<<(EE + 7) / 8, 256>>>(src, dst, ph1, pa1);
    k_scatter<<<(EE + 7) / 8, 256>>>(src, dst, ph2, pa2);

    // GraphConv1: h1b = h1@w2_root + agg1@w2_rel + b2
    k_cvtB<<<(CC * CC + 255) / 256, 256>>>(w2_root, CC, CC, 0);
    k_cvtB<<<(CC * CC + 255) / 256, 256>>>(w2_rel, CC, CC, B1);
    gemmM(NN, CC, CC, 2, ph1, pa1, nullptr, 0, B1, 0, ph1b, b2, 0, 0);

    // GraphConv2
    k_cvtB<<<(CC * CC + 255) / 256, 256>>>(w4_root, CC, CC, 0);
    k_cvtB<<<(CC * CC + 255) / 256, 256>>>(w4_rel, CC, CC, B1);
    gemmM(NN, CC, CC, 2, ph2, pa2, nullptr, 0, B1, 0, ph2b, b4, 0, 0);

    // MLP layer 1: one launch over concat([enc, h1b, h2b])
    k_cvtB<<<(CC * 128 + 255) / 256, 256>>>(wd1,             CC, 128, 0);
    k_cvtB<<<(CC * 128 + 255) / 256, 256>>>(wd1 + 256 * 128, CC, 128, B1);
    k_cvtB<<<(CC * 128 + 255) / 256, 256>>>(wd1 + 512 * 128, CC, 128, B2);
    gemmM(NN, 128, CC, 3, enc, ph1b, ph2b, 0, B1, B2, pm1, bd1, 0, 1);

    // MLP layer 2
    k_cvtB<<<(128 * 64 + 255) / 256, 256>>>(wd2, 128, 64, 0);
    gemmM(NN, 64, 128, 1, pm1, nullptr, nullptr, 0, 0, 0, pm2, bd2, 0, 1);

    k_final<<<(NN + 7) / 8, 256>>>(wd3, bd3, out);

    (void)in_sizes; (void)n_in; (void)out_size;
}

// round 17
// speedup vs baseline: 1.1032x; 1.1032x over previous
#include <cuda_runtime.h>
#include <cuda_fp16.h>
#include <cstdint>

#define NN 60000
#define EE 480000
#define CC 256
#define RR 16
#define XWW 8192
#define NB1 (NN*RR)
#define AGGROWS 245760000
#define MAXT 7600
#define PITCH 40

// ---------------- scratch ----------------
__device__ float g_x   [(size_t)NN*CC];
__device__ float g_xw  [(size_t)NN*XWW];
__device__ float g_h1  [(size_t)NN*CC];
__device__ float g_h2  [(size_t)NN*CC];
__device__ float g_h1b [(size_t)NN*CC];
__device__ float g_h2b [(size_t)NN*CC];
__device__ float g_agg1[(size_t)NN*CC];
__device__ float g_agg2[(size_t)NN*CC];
__device__ float g_m1  [(size_t)NN*128];
__device__ float g_m2  [(size_t)NN*64];
__device__ int   g_cnt1[NB1];
__device__ int   g_cnt3[NB1];
__device__ int   g_slot[2*NB1];
__device__ int   g_rowdst[2*NB1];
__device__ int   g_relcnt[32];
__device__ int   g_relfill[32];
__device__ int   g_tr[2*MAXT];
__device__ int   g_tb[2*MAXT];
__device__ int   g_tn[2*MAXT];
__device__ int   g_ntiles[2];
__device__ int   g_reloff[34];
__device__ __half g_wt[(size_t)XWW*CC];   // W^T fp16 [8192,256]
__device__ __half g_bb[3*65536];          // small B^T fp16 staging

// ---------------- helpers ----------------
__device__ __forceinline__ uint32_t smem_u32(const void* p) {
    uint32_t a;
    asm("{ .reg .u64 t; cvta.to.shared.u64 t, %1; cvt.u32.u64 %0, t; }" : "=r"(a) : "l"(p));
    return a;
}
__device__ __forceinline__ void ldx4(uint32_t addr, uint32_t& r0, uint32_t& r1,
                                     uint32_t& r2, uint32_t& r3) {
    asm volatile("ldmatrix.sync.aligned.m8n8.x4.shared.b16 {%0,%1,%2,%3}, [%4];"
                 : "=r"(r0), "=r"(r1), "=r"(r2), "=r"(r3) : "r"(addr));
}
__device__ __forceinline__ void mma16816h(float* c, const uint32_t* a, const uint32_t* b) {
    asm volatile(
        "mma.sync.aligned.m16n8k16.row.col.f32.f16.f16.f32 "
        "{%0,%1,%2,%3}, {%4,%5,%6,%7}, {%8,%9}, {%0,%1,%2,%3};"
        : "+f"(c[0]), "+f"(c[1]), "+f"(c[2]), "+f"(c[3])
        : "r"(a[0]), "r"(a[1]), "r"(a[2]), "r"(a[3]), "r"(b[0]), "r"(b[1]));
}
// fp32x4 -> fp16 hi/lo packed pairs
__device__ __forceinline__ void split4h(float4 v, uint2& ph, uint2& pl) {
    __half h0 = __float2half_rn(v.x), h1 = __float2half_rn(v.y);
    __half h2 = __float2half_rn(v.z), h3 = __float2half_rn(v.w);
    __half l0 = __float2half_rn(v.x - __half2float(h0));
    __half l1 = __float2half_rn(v.y - __half2float(h1));
    __half l2 = __float2half_rn(v.z - __half2float(h2));
    __half l3 = __float2half_rn(v.w - __half2float(h3));
    ph.x = (uint32_t)__half_as_ushort(h0) | ((uint32_t)__half_as_ushort(h1) << 16);
    ph.y = (uint32_t)__half_as_ushort(h2) | ((uint32_t)__half_as_ushort(h3) << 16);
    pl.x = (uint32_t)__half_as_ushort(l0) | ((uint32_t)__half_as_ushort(l1) << 16);
    pl.y = (uint32_t)__half_as_ushort(l2) | ((uint32_t)__half_as_ushort(l3) << 16);
}

// ---------------- small kernels ----------------
__global__ void k_zero() {
    int i = blockIdx.x * blockDim.x + threadIdx.x;
    int stride = gridDim.x * blockDim.x;
    const int nf = NN * CC;
    for (int j = i; j < nf; j += stride) {
        g_h1[j] = 0.f; g_h2[j] = 0.f; g_agg1[j] = 0.f; g_agg2[j] = 0.f;
    }
    for (int j = i; j < NB1; j += stride) { g_cnt1[j] = 0; g_cnt3[j] = 0; }
    if (i < 32) { g_relcnt[i] = 0; g_relfill[i] = 0; }
}

__global__ void k_hist(const int* __restrict__ dst, const int* __restrict__ et1,
                       const int* __restrict__ et3) {
    int e = blockIdx.x * blockDim.x + threadIdx.x;
    if (e >= EE) return;
    int d = dst[e];
    atomicAdd(&g_cnt1[d * RR + et1[e]], 1);
    atomicAdd(&g_cnt3[d * RR + et3[e]], 1);
}

__global__ void k_nonempty() {
    int idx = blockIdx.x * blockDim.x + threadIdx.x;
    if (idx >= 2 * NB1) return;
    int q = idx / NB1, b = idx - q * NB1;
    int c = q ? g_cnt3[b] : g_cnt1[b];
    if (c > 0) atomicAdd(&g_relcnt[q * 16 + (b & 15)], 1);
}

__global__ void k_buildtiles() {
    __shared__ int s_off[32], s_toff[32];
    int t = threadIdx.x;
    if (t == 0) {
        for (int q = 0; q < 2; q++) {
            int off = 0, toff = 0;
            for (int r = 0; r < 16; r++) {
                int i = q * 16 + r;
                s_off[i] = off; s_toff[i] = toff;
                int c = g_relcnt[i];
                g_reloff[q * 17 + r] = off;
                off += c;
                toff += (c + 127) >> 7;
            }
            g_reloff[q * 17 + 16] = off;
            g_ntiles[q] = toff;
        }
    }
    __syncthreads();
    int q = t >> 4, r = t & 15;
    int c = g_relcnt[t];
    int base = s_off[t], tile0 = s_toff[t];
    int nt = (c + 127) >> 7;
    for (int k = 0; k < nt; k++) {
        int idx = q * MAXT + tile0 + k;
        g_tr[idx] = r;
        g_tb[idx] = base + k * 128;
        g_tn[idx] = min(128, c - k * 128);
    }
}

__global__ void k_zeroagg() {
    size_t n0 = (size_t)g_reloff[16] * 64;
    size_t n1 = (size_t)g_reloff[33] * 64;
    size_t stride = (size_t)gridDim.x * blockDim.x;
    size_t i0 = (size_t)blockIdx.x * blockDim.x + threadIdx.x;
    float4 z = make_float4(0.f, 0.f, 0.f, 0.f);
    float4* p0 = (float4*)g_xw;
    float4* p1 = (float4*)(g_xw + (size_t)AGGROWS);
    for (size_t i = i0; i < n0; i += stride) p0[i] = z;
    for (size_t i = i0; i < n1; i += stride) p1[i] = z;
}

__global__ void k_slot() {
    int idx = blockIdx.x * blockDim.x + threadIdx.x;
    if (idx >= 2 * NB1) return;
    int q = idx / NB1, b = idx - q * NB1;
    int c = q ? g_cnt3[b] : g_cnt1[b];
    if (c <= 0) return;
    int r = b & 15;
    int s = g_reloff[q * 17 + r] + atomicAdd(&g_relfill[q * 16 + r], 1);
    g_slot[idx] = s;
    g_rowdst[q * NB1 + s] = b >> 4;
}

__global__ void k_cvtX(const float* __restrict__ enc, const int* __restrict__ spk,
                       const float* __restrict__ table) {
    int i = blockIdx.x * blockDim.x + threadIdx.x;
    if (i >= NN * CC / 4) return;
    int n = i >> 6, c = i & 63;
    float4 e = ((const float4*)enc)[i];
    float4 t = ((const float4*)table)[spk[n] * 64 + c];
    e.x += t.x; e.y += t.y; e.z += t.z; e.w += t.w;
    ((float4*)g_x)[i] = e;
}

// build W_cat^T fp16: row n=(r*256+o), col k=i
__global__ void k_packW(const float* __restrict__ bases1, const float* __restrict__ comp1,
                        const float* __restrict__ bases3, const float* __restrict__ comp3) {
    int r = blockIdx.x;
    int i0 = blockIdx.y * 8;
    int o = threadIdx.x;
    const float* bases = (r < 16) ? bases1 : bases3;
    const float* comp  = (r < 16) ? comp1  : comp3;
    int rr = r & 15;
    float cf[8];
#pragma unroll
    for (int b = 0; b < 8; b++) cf[b] = comp[rr * 8 + b];
    for (int i = i0; i < i0 + 8; i++) {
        float acc = 0.f;
#pragma unroll
        for (int b = 0; b < 8; b++) acc += cf[b] * bases[b * 65536 + i * 256 + o];
        g_wt[(size_t)(r * 256 + o) * CC + i] = __float2half_rn(acc);
    }
}

// fp32 weight [K,N] row-major -> B^T fp16 [N,K] at offset
__global__ void k_cvtB(const float* __restrict__ in, int K, int N, int off) {
    int idx = blockIdx.x * blockDim.x + threadIdx.x;
    if (idx >= N * K) return;
    int n = idx / K, k = idx - n * K;
    g_bb[off + idx] = __float2half_rn(in[(size_t)k * N + n]);
}

__global__ void k_edgeagg(const int* __restrict__ src, const int* __restrict__ dst,
                          const int* __restrict__ et, const int* __restrict__ est) {
    int e = blockIdx.x * (blockDim.x >> 5) + (threadIdx.x >> 5);
    int lane = threadIdx.x & 31;
    if (e >= EE) return;
    int s = src[e], d = dst[e];
    int b1 = d * RR + et[e], b3 = d * RR + est[e];
    int s1 = g_slot[b1], s3 = g_slot[NB1 + b3];
    float n1 = 1.f / (float)g_cnt1[b1];
    float n3 = 1.f / (float)g_cnt3[b3];
    const float4* xr = (const float4*)(g_x + (size_t)s * CC);
    float* a1 = g_xw + (size_t)s1 * CC;
    float* a3 = g_xw + (size_t)AGGROWS + (size_t)s3 * CC;
#pragma unroll
    for (int k = 0; k < 2; k++) {
        int o4 = lane + k * 32;
        float4 v = xr[o4];
        asm volatile("red.global.add.v4.f32 [%0], {%1,%2,%3,%4};"
                     :: "l"(a1 + o4 * 4), "f"(v.x * n1), "f"(v.y * n1),
                        "f"(v.z * n1), "f"(v.w * n1) : "memory");
        asm volatile("red.global.add.v4.f32 [%0], {%1,%2,%3,%4};"
                     :: "l"(a3 + o4 * 4), "f"(v.x * n3), "f"(v.y * n3),
                        "f"(v.z * n3), "f"(v.w * n3) : "memory");
    }
}

__global__ void k_scatter(const int* __restrict__ src, const int* __restrict__ dst,
                          const float* __restrict__ h, float* __restrict__ agg) {
    int e = blockIdx.x * (blockDim.x >> 5) + (threadIdx.x >> 5);
    int lane = threadIdx.x & 31;
    if (e >= EE) return;
    const float4* hr = (const float4*)(h + (size_t)src[e] * CC);
    float* ap = agg + (size_t)dst[e] * CC;
#pragma unroll
    for (int k = 0; k < 2; k++) {
        int o4 = lane + k * 32;
        float4 v = hr[o4];
        asm volatile("red.global.add.v4.f32 [%0], {%1,%2,%3,%4};"
                     :: "l"(ap + o4 * 4), "f"(v.x), "f"(v.y), "f"(v.z), "f"(v.w) : "memory");
    }
}

// ---------------- tile-list RGCN GEMM + scatter (fp16 2-MMA) ----------------
__global__ __launch_bounds__(256) void tcrgemm() {
    int q = blockIdx.z;
    if ((int)blockIdx.x >= g_ntiles[q]) return;
    int tid = threadIdx.x, wid = tid >> 5, lane = tid & 31;
    int ti = q * MAXT + blockIdx.x;
    int rel = g_tr[ti], mbase = g_tb[ti], mrows = g_tn[ti];
    const float* A = g_xw + (size_t)q * AGGROWS + (size_t)mbase * CC;
    const __half* B = g_wt + ((size_t)(q * 16 + rel) * 256 + blockIdx.y * 128) * CC;
    float* H = q ? g_h2 : g_h1;
    const int* rowdst = g_rowdst + q * NB1 + mbase;

    __shared__ __align__(16) __half sAh[128 * PITCH];
    __shared__ __align__(16) __half sAl[128 * PITCH];
    __shared__ __align__(16) __half sB [128 * PITCH];

    int wm = (wid >> 2) * 64, wn = (wid & 3) * 32;
    float acc[4][4][4];
#pragma unroll
    for (int i = 0; i < 4; i++)
#pragma unroll
        for (int j = 0; j < 4; j++)
#pragma unroll
            for (int k = 0; k < 4; k++) acc[i][j][k] = 0.f;

    uint32_t uA0 = smem_u32(sAh), uA1 = smem_u32(sAl);
    uint32_t uB0 = smem_u32(sB);

    int arow = tid >> 1, ahalf = tid & 1;
    bool avalid = arow < mrows;

    for (int ch = 0; ch < 8; ch++) {
        int k0 = ch << 5;
        {
            const float4* ap = (const float4*)(A + (size_t)arow * CC + k0 + ahalf * 16);
#pragma unroll
            for (int j = 0; j < 4; j++) {
                float4 f = avalid ? ap[j] : make_float4(0.f, 0.f, 0.f, 0.f);
                uint2 ph, pl;
                split4h(f, ph, pl);
                int off = arow * PITCH + ahalf * 16 + j * 4;
                *(uint2*)(sAh + off) = ph;
                *(uint2*)(sAl + off) = pl;
            }
        }
#pragma unroll
        for (int i = 0; i < 2; i++) {
            int w = (i << 8) + tid;
            int row = w >> 2, c = w & 3;
            uint4 val = *(const uint4*)(B + (size_t)row * CC + k0 + c * 8);
            *(uint4*)(sB + row * PITCH + c * 8) = val;
        }
        __syncthreads();
#pragma unroll
        for (int ks = 0; ks < 2; ks++) {
            int kb = ks * 32;
            uint32_t bfr[4][2];
#pragma unroll
            for (int pair = 0; pair < 2; pair++) {
                int nrow = wn + pair * 16 + ((lane >> 4) & 1) * 8 + (lane & 7);
                int kbyte = kb + ((lane >> 3) & 1) * 16;
                uint32_t off = nrow * (PITCH * 2) + kbyte;
                ldx4(uB0 + off, bfr[pair * 2][0], bfr[pair * 2][1],
                     bfr[pair * 2 + 1][0], bfr[pair * 2 + 1][1]);
            }
#pragma unroll
            for (int mt = 0; mt < 4; mt++) {
                int ar = wm + mt * 16 + (lane & 15);
                int kbyte = kb + ((lane >> 4) & 1) * 16;
                uint32_t off = ar * (PITCH * 2) + kbyte;
                uint32_t ah[4], al[4];
                ldx4(uA0 + off, ah[0], ah[1], ah[2], ah[3]);
                ldx4(uA1 + off, al[0], al[1], al[2], al[3]);
#pragma unroll
                for (int nt = 0; nt < 4; nt++) {
                    mma16816h(acc[mt][nt], ah, bfr[nt]);
                    mma16816h(acc[mt][nt], al, bfr[nt]);
                }
            }
        }
        __syncthreads();
    }

    int tr = lane >> 2, tc = (lane & 3) * 2;
    int col0 = blockIdx.y * 128;
#pragma unroll
    for (int mt = 0; mt < 4; mt++) {
#pragma unroll
        for (int half = 0; half < 2; half++) {
            int rl = wm + mt * 16 + tr + half * 8;
            if (rl >= mrows) continue;
            int d = rowdst[rl];
            float* hp = H + (size_t)d * CC + col0 + wn;
#pragma unroll
            for (int nt = 0; nt < 4; nt++) {
                float v0 = acc[mt][nt][half * 2 + 0];
                float v1 = acc[mt][nt][half * 2 + 1];
                asm volatile("red.global.add.v2.f32 [%0], {%1,%2};"
                             :: "l"(hp + nt * 8 + tc), "f"(v0), "f"(v1) : "memory");
            }
        }
    }
}

// ---------------- multi-source fp32-A HMMA GEMM (fp16 2-MMA) ----------------
__global__ __launch_bounds__(256) void hgemmM(
    int M, int Nt, int K, int ns,
    const float* __restrict__ A0, const float* __restrict__ A1, const float* __restrict__ A2,
    const __half* __restrict__ B0, const __half* __restrict__ B1,
    const __half* __restrict__ B2,
    float* __restrict__ C, const float* __restrict__ bias, int accf, int reluf)
{
    __shared__ __align__(16) __half sAh[128 * PITCH];
    __shared__ __align__(16) __half sAl[128 * PITCH];
    __shared__ __align__(16) __half sB [128 * PITCH];

    int tid = threadIdx.x, wid = tid >> 5, lane = tid & 31;
    int m0 = blockIdx.y * 128, n0 = blockIdx.x * 128;
    int wm = (wid >> 2) * 64, wn = (wid & 3) * 32;

    float acc[4][4][4];
#pragma unroll
    for (int i = 0; i < 4; i++)
#pragma unroll
        for (int j = 0; j < 4; j++)
#pragma unroll
            for (int k = 0; k < 4; k++) acc[i][j][k] = 0.f;

    uint32_t uA0 = smem_u32(sAh), uA1 = smem_u32(sAl);
    uint32_t uB0 = smem_u32(sB);

    int arow = tid >> 1, ahalf = tid & 1;
    bool avalid = (m0 + arow) < M;
    int kc = K >> 5;

    for (int s = 0; s < ns; s++) {
        const float* As = (s == 0) ? A0 : (s == 1) ? A1 : A2;
        const __half* Bs = (s == 0) ? B0 : (s == 1) ? B1 : B2;
        for (int ch = 0; ch < kc; ch++) {
            int k0 = ch << 5;
            {
                const float4* ap = (const float4*)(As + (size_t)(m0 + arow) * K + k0 + ahalf * 16);
#pragma unroll
                for (int j = 0; j < 4; j++) {
                    float4 f = avalid ? ap[j] : make_float4(0.f, 0.f, 0.f, 0.f);
                    uint2 ph, pl;
                    split4h(f, ph, pl);
                    int off = arow * PITCH + ahalf * 16 + j * 4;
                    *(uint2*)(sAh + off) = ph;
                    *(uint2*)(sAl + off) = pl;
                }
            }
#pragma unroll
            for (int i = 0; i < 2; i++) {
                int w = (i << 8) + tid;
                int row = w >> 2, c = w & 3;
                uint4 val = (n0 + row < Nt)
                          ? *(const uint4*)(Bs + (size_t)(n0 + row) * K + k0 + c * 8)
                          : make_uint4(0, 0, 0, 0);
                *(uint4*)(sB + row * PITCH + c * 8) = val;
            }
            __syncthreads();
#pragma unroll
            for (int ks = 0; ks < 2; ks++) {
                int kb = ks * 32;
                uint32_t bfr[4][2];
#pragma unroll
                for (int pair = 0; pair < 2; pair++) {
                    int nrow = wn + pair * 16 + ((lane >> 4) & 1) * 8 + (lane & 7);
                    int kbyte = kb + ((lane >> 3) & 1) * 16;
                    uint32_t off = nrow * (PITCH * 2) + kbyte;
                    ldx4(uB0 + off, bfr[pair * 2][0], bfr[pair * 2][1],
                         bfr[pair * 2 + 1][0], bfr[pair * 2 + 1][1]);
                }
#pragma unroll
                for (int mt = 0; mt < 4; mt++) {
                    int ar = wm + mt * 16 + (lane & 15);
                    int kbyte = kb + ((lane >> 4) & 1) * 16;
                    uint32_t off = ar * (PITCH * 2) + kbyte;
                    uint32_t ah[4], al[4];
                    ldx4(uA0 + off, ah[0], ah[1], ah[2], ah[3]);
                    ldx4(uA1 + off, al[0], al[1], al[2], al[3]);
#pragma unroll
                    for (int nt = 0; nt < 4; nt++) {
                        mma16816h(acc[mt][nt], ah, bfr[nt]);
                        mma16816h(acc[mt][nt], al, bfr[nt]);
                    }
                }
            }
            __syncthreads();
        }
    }

    int tr = lane >> 2, tc = (lane & 3) * 2;
#pragma unroll
    for (int mt = 0; mt < 4; mt++) {
#pragma unroll
        for (int nt = 0; nt < 4; nt++) {
            int c = n0 + wn + nt * 8 + tc;
            if (c >= Nt) continue;
#pragma unroll
            for (int half = 0; half < 2; half++) {
                int r = m0 + wm + mt * 16 + tr + half * 8;
                if (r >= M) continue;
                float v0 = acc[mt][nt][half * 2 + 0];
                float v1 = acc[mt][nt][half * 2 + 1];
                float* cp = C + (size_t)r * Nt + c;
                if (accf) { float2 o = *(const float2*)cp; v0 += o.x; v1 += o.y; }
                if (bias) { v0 += bias[c]; v1 += bias[c + 1]; }
                if (reluf) { v0 = fmaxf(v0, 0.f); v1 = fmaxf(v1, 0.f); }
                float2 w2 = make_float2(v0, v1);
                *(float2*)cp = w2;
            }
        }
    }
}

__global__ void k_final(const float* __restrict__ wd3, const float* __restrict__ bd3,
                        float* __restrict__ out) {
    int n = blockIdx.x * (blockDim.x >> 5) + (threadIdx.x >> 5);
    int lane = threadIdx.x & 31;
    if (n >= NN) return;
    const float* m = g_m2 + (size_t)n * 64;
    float s = m[lane] * wd3[lane] + m[lane + 32] * wd3[lane + 32];
#pragma unroll
    for (int o = 16; o; o >>= 1) s += __shfl_xor_sync(0xffffffffu, s, o);
    if (lane == 0) out[n] = s + bd3[0];
}

// ---------------- host ----------------
static __half* pbb;

static void gemmM(int M, int Nt, int K, int ns,
                  const float* A0, const float* A1, const float* A2,
                  int off0, int off1, int off2,
                  float* C, const float* bias, int acc, int relu) {
    dim3 g((Nt + 127) / 128, (M + 127) / 128);
    hgemmM<<<g, 256>>>(M, Nt, K, ns, A0, A1, A2,
                       pbb + off0, pbb + off1, pbb + off2, C, bias, acc, relu);
}

extern "C" void kernel_launch(void* const* d_in, const int* in_sizes, int n_in,
                              void* d_out, int out_size) {
    const float* enc     = (const float*)d_in[0];
    const int*   speaker = (const int*)d_in[1];
    const int*   eidx    = (const int*)d_in[2];
    const int*   src     = eidx;
    const int*   dst     = eidx + EE;
    const int*   et      = (const int*)d_in[3];
    const int*   est     = (const int*)d_in[4];
    const float* spk_tab = (const float*)d_in[5];
    const float* comp1   = (const float*)d_in[6];
    const float* bases1  = (const float*)d_in[7];
    const float* root1   = (const float*)d_in[8];
    const float* b1      = (const float*)d_in[9];
    const float* w2_rel  = (const float*)d_in[10];
    const float* b2      = (const float*)d_in[11];
    const float* w2_root = (const float*)d_in[12];
    const float* comp3   = (const float*)d_in[13];
    const float* bases3  = (const float*)d_in[14];
    const float* root3   = (const float*)d_in[15];
    const float* b3      = (const float*)d_in[16];
    const float* w4_rel  = (const float*)d_in[17];
    const float* b4      = (const float*)d_in[18];
    const float* w4_root = (const float*)d_in[19];
    const float* wd1     = (const float*)d_in[20];
    const float* bd1     = (const float*)d_in[21];
    const float* wd2     = (const float*)d_in[22];
    const float* bd2     = (const float*)d_in[23];
    const float* wd3     = (const float*)d_in[24];
    const float* bd3     = (const float*)d_in[25];
    float* out = (float*)d_out;

    float *px, *ph1, *ph2, *ph1b, *ph2b, *pa1, *pa2, *pm1, *pm2;
    cudaGetSymbolAddress((void**)&px,   g_x);
    cudaGetSymbolAddress((void**)&ph1,  g_h1);
    cudaGetSymbolAddress((void**)&ph2,  g_h2);
    cudaGetSymbolAddress((void**)&ph1b, g_h1b);
    cudaGetSymbolAddress((void**)&ph2b, g_h2b);
    cudaGetSymbolAddress((void**)&pa1,  g_agg1);
    cudaGetSymbolAddress((void**)&pa2,  g_agg2);
    cudaGetSymbolAddress((void**)&pm1,  g_m1);
    cudaGetSymbolAddress((void**)&pm2,  g_m2);
    cudaGetSymbolAddress((void**)&pbb,  g_bb);

    const int NC4 = NN * CC / 4;
    const int B1 = 65536, B2 = 131072;

    k_zero<<<2048, 256>>>();
    k_cvtX<<<(NC4 + 255) / 256, 256>>>(enc, speaker, spk_tab);
    k_hist<<<(EE + 255) / 256, 256>>>(dst, et, est);
    k_packW<<<dim3(32, 32), 256>>>(bases1, comp1, bases3, comp3);

    // bucket compaction
    k_nonempty<<<(2 * NB1 + 255) / 256, 256>>>();
    k_buildtiles<<<1, 32>>>();
    k_zeroagg<<<8192, 256>>>();
    k_slot<<<(2 * NB1 + 255) / 256, 256>>>();

    // per-edge aggregation + compacted RGCN GEMMs
    k_edgeagg<<<(EE + 7) / 8, 256>>>(src, dst, et, est);
    tcrgemm<<<dim3(MAXT, 2, 2), 256>>>();

    // root terms: h += x@root + b
    k_cvtB<<<(CC * CC + 255) / 256, 256>>>(root1, CC, CC, 0);
    gemmM(NN, CC, CC, 1, px, nullptr, nullptr, 0, 0, 0, ph1, b1, 1, 0);
    k_cvtB<<<(CC * CC + 255) / 256, 256>>>(root3, CC, CC, 0);
    gemmM(NN, CC, CC, 1, px, nullptr, nullptr, 0, 0, 0, ph2, b3, 1, 0);

    // GraphConv aggregations
    k_scatter<<<(EE + 7) / 8, 256>>>(src, dst, ph1, pa1);
    k_scatter<<<(EE + 7) / 8, 256>>>(src, dst, ph2, pa2);

    // GraphConv1: h1b = h1@w2_root + agg1@w2_rel + b2
    k_cvtB<<<(CC * CC + 255) / 256, 256>>>(w2_root, CC, CC, 0);
    k_cvtB<<<(CC * CC + 255) / 256, 256>>>(w2_rel, CC, CC, B1);
    gemmM(NN, CC, CC, 2, ph1, pa1, nullptr, 0, B1, 0, ph1b, b2, 0, 0);

    // GraphConv2
    k_cvtB<<<(CC * CC + 255) / 256, 256>>>(w4_root, CC, CC, 0);
    k_cvtB<<<(CC * CC + 255) / 256, 256>>>(w4_rel, CC, CC, B1);
    gemmM(NN, CC, CC, 2, ph2, pa2, nullptr, 0, B1, 0, ph2b, b4, 0, 0);

    // MLP layer 1: one launch over concat([enc, h1b, h2b])
    k_cvtB<<<(CC * 128 + 255) / 256, 256>>>(wd1,             CC, 128, 0);
    k_cvtB<<<(CC * 128 + 255) / 256, 256>>>(wd1 + 256 * 128, CC, 128, B1);
    k_cvtB<<<(CC * 128 + 255) / 256, 256>>>(wd1 + 512 * 128, CC, 128, B2);
    gemmM(NN, 128, CC, 3, enc, ph1b, ph2b, 0, B1, B2, pm1, bd1, 0, 1);

    // MLP layer 2
    k_cvtB<<<(128 * 64 + 255) / 256, 256>>>(wd2, 128, 64, 0);
    gemmM(NN, 64, 128, 1, pm1, nullptr, nullptr, 0, 0, 0, pm2, bd2, 0, 1);

    k_final<<<(NN + 7) / 8, 256>>>(wd3, bd3, out);

    (void)in_sizes; (void)n_in; (void)out_size;
}